// round 11
// baseline (speedup 1.0000x reference)
#include <cuda_runtime.h>
#include <cstdint>

#define DIM 512
#define BATCH 32
#define M_TOTAL 131072            /* 64*64*32 */
#define MTILE 128
#define KC 32                      /* k per chunk */
#define NCHUNK (DIM/KC)            /* 16 */
#define NTHREADS 128
#define A_STRIDE 36                /* words per A smem row: banks (4g+tg)%32 bijective */
#define B_WORDS (DIM*BATCH)        /* 16384 words = 64KB fragment-ordered B in gmem/L2 */

/* B in per-lane MMA fragment order (L2-resident, read by every CTA):
   g_bfrag[(kstep*2+h)*128 + lid*4 + nt] = rna_tf32(L[k]*style[b][k])
   with k = kstep*8 + (lid&3) + 4h, b = nt*8 + (lid>>2), kstep = 0..63. */
__device__ uint32_t g_bfrag[B_WORDS];

__global__ void prep_kernel(const float* __restrict__ style, const float* __restrict__ L) {
    int i = blockIdx.x * blockDim.x + threadIdx.x;
    if (i < B_WORDS) {
        int nt    = i & 3;
        int lid   = (i >> 2) & 31;
        int h     = (i >> 7) & 1;
        int kstep = i >> 8;
        int k = kstep * 8 + (lid & 3) + h * 4;
        int b = nt * 8 + (lid >> 2);
        float v = L[k] * style[b * DIM + k];
        uint32_t bits;
        asm("cvt.rna.tf32.f32 %0, %1;" : "=r"(bits) : "f"(v));
        g_bfrag[i] = bits;
    }
}

__device__ __forceinline__ uint32_t smem_u32(const void* p) {
    return (uint32_t)__cvta_generic_to_shared(p);
}
__device__ __forceinline__ void cp16(uint32_t dst, const void* src) {
    asm volatile("cp.async.cg.shared.global [%0], [%1], 16;" :: "r"(dst), "l"(src));
}
__device__ __forceinline__ void cp_commit() {
    asm volatile("cp.async.commit_group;" ::: "memory");
}
__device__ __forceinline__ void cp_wait1() {
    asm volatile("cp.async.wait_group 1;" ::: "memory");
}
__device__ __forceinline__ void mma_tf32(float* d, const uint32_t* a, uint32_t b0, uint32_t b1) {
    asm volatile(
        "mma.sync.aligned.m16n8k8.row.col.f32.tf32.tf32.f32 "
        "{%0,%1,%2,%3}, {%4,%5,%6,%7}, {%8,%9}, {%0,%1,%2,%3};"
        : "+f"(d[0]), "+f"(d[1]), "+f"(d[2]), "+f"(d[3])
        : "r"(a[0]), "r"(a[1]), "r"(a[2]), "r"(a[3]), "r"(b0), "r"(b1));
}

__global__ void __launch_bounds__(NTHREADS, 4)
gemm_kernel(const float* __restrict__ U, const float* __restrict__ mu, float* __restrict__ out)
{
    __shared__ uint32_t sA[2][MTILE * A_STRIDE];   /* 2 x 18 KB, padded rows; no B smem */

    const int tid = threadIdx.x;
    const int wid = tid >> 5;
    const int lid = tid & 31;
    const int g   = lid >> 2;      /* groupID 0..7 */
    const int tg  = lid & 3;       /* thread-in-group 0..3 */
    const int mbase = blockIdx.x * MTILE;

    /* A-only cp.async prefetch (exact R3 pattern) */
    auto prefetchA = [&](int c, int buf) {
        const float* ubase = U + (size_t)mbase * DIM + c * KC;
        uint32_t adst = smem_u32(&sA[buf][0]);
        #pragma unroll
        for (int j = 0; j < 8; ++j) {
            int id  = j * NTHREADS + tid;
            int row = id >> 3, seg = id & 7;
            cp16(adst + (uint32_t)(row * (A_STRIDE * 4) + seg * 16),
                 ubase + (size_t)row * DIM + seg * 4);
        }
    };

    float acc[2][4][4];
    #pragma unroll
    for (int mt = 0; mt < 2; ++mt)
        #pragma unroll
        for (int nt = 0; nt < 4; ++nt)
            #pragma unroll
            for (int r = 0; r < 4; ++r) acc[mt][nt][r] = 0.0f;

    prefetchA(0, 0); cp_commit();
    prefetchA(1, 1); cp_commit();

    for (int c = 0; c < NCHUNK; ++c) {
        cp_wait1();
        __syncthreads();            /* A(c) resident & visible to all warps */
        const int buf = c & 1;
        const uint32_t* A = sA[buf];

        /* B fragments for all 4 k-steps: 8x coalesced LDG.128 from L2-resident
           fragment array; issued up-front so latency hides under the MMAs. */
        uint4 bf[4][2];
        #pragma unroll
        for (int ks = 0; ks < 4; ++ks) {
            int kstep = c * 4 + ks;
            bf[ks][0] = *(const uint4*)&g_bfrag[(kstep * 2    ) * 128 + lid * 4];
            bf[ks][1] = *(const uint4*)&g_bfrag[(kstep * 2 + 1) * 128 + lid * 4];
        }

        #pragma unroll
        for (int ks = 0; ks < 4; ++ks) {
            uint32_t a[2][4];
            #pragma unroll
            for (int mt = 0; mt < 2; ++mt) {
                int rb = wid * 32 + mt * 16;
                /* +0x1000: RNE into tf32 (HW truncates low 13 bits) */
                a[mt][0] = A[(rb + g)     * A_STRIDE + ks * 8 + tg]     + 0x1000u;
                a[mt][1] = A[(rb + g + 8) * A_STRIDE + ks * 8 + tg]     + 0x1000u;
                a[mt][2] = A[(rb + g)     * A_STRIDE + ks * 8 + tg + 4] + 0x1000u;
                a[mt][3] = A[(rb + g + 8) * A_STRIDE + ks * 8 + tg + 4] + 0x1000u;
            }
            #pragma unroll
            for (int mt = 0; mt < 2; ++mt) {
                mma_tf32(acc[mt][0], a[mt], bf[ks][0].x, bf[ks][1].x);
                mma_tf32(acc[mt][1], a[mt], bf[ks][0].y, bf[ks][1].y);
                mma_tf32(acc[mt][2], a[mt], bf[ks][0].z, bf[ks][1].z);
                mma_tf32(acc[mt][3], a[mt], bf[ks][0].w, bf[ks][1].w);
            }
        }

        __syncthreads();            /* all warps done reading sA[buf] */
        if (c + 2 < NCHUNK) prefetchA(c + 2, buf);
        cp_commit();                /* possibly-empty group: uniform accounting */
    }

    /* epilogue: add mu, store out[b][m] */
    #pragma unroll
    for (int mt = 0; mt < 2; ++mt) {
        int m0 = mbase + wid * 32 + mt * 16 + g;
        float mu0 = __ldg(&mu[m0]);
        float mu1 = __ldg(&mu[m0 + 8]);
        #pragma unroll
        for (int nt = 0; nt < 4; ++nt) {
            int bb = nt * 8 + 2 * tg;
            out[(size_t)bb       * M_TOTAL + m0]     = acc[mt][nt][0] + mu0;
            out[(size_t)(bb + 1) * M_TOTAL + m0]     = acc[mt][nt][1] + mu0;
            out[(size_t)bb       * M_TOTAL + m0 + 8] = acc[mt][nt][2] + mu1;
            out[(size_t)(bb + 1) * M_TOTAL + m0 + 8] = acc[mt][nt][3] + mu1;
        }
    }
}

extern "C" void kernel_launch(void* const* d_in, const int* in_sizes, int n_in,
                              void* d_out, int out_size) {
    const float *style = nullptr, *U = nullptr, *L = nullptr, *mu = nullptr;
    for (int i = 0; i < n_in; ++i) {
        switch (in_sizes[i]) {
            case BATCH * DIM:   style = (const float*)d_in[i]; break;
            case M_TOTAL * DIM: U     = (const float*)d_in[i]; break;
            case DIM:           L     = (const float*)d_in[i]; break;
            case M_TOTAL:       mu    = (const float*)d_in[i]; break;
            default: break;
        }
    }
    float* out = (float*)d_out;

    prep_kernel<<<(B_WORDS + 255) / 256, 256>>>(style, L);
    gemm_kernel<<<M_TOTAL / MTILE, NTHREADS>>>(U, mu, out);
}

// round 12
// speedup vs baseline: 1.1405x; 1.1405x over previous
#include <cuda_runtime.h>
#include <cstdint>

#define DIM 512
#define BATCH 32
#define M_TOTAL 131072            /* 64*64*32 */
#define MTILE 128
#define KC 32                      /* k per chunk */
#define NCHUNK (DIM/KC)            /* 16 */
#define NTHREADS 128
#define A_STRIDE 36                /* words per A smem row: banks (4g+tg)%32 bijective */
#define B_STRIDE 40                /* words per B smem row: banks (8tg+g)%32 bijective */

/* B operand, tf32-RNE: g_scaled[k*32+b] = rna_tf32(L[k]*style[b][k])  (k-major) */
__device__ uint32_t g_scaled[DIM * BATCH];

__global__ void prep_kernel(const float* __restrict__ style, const float* __restrict__ L) {
    int i = blockIdx.x * blockDim.x + threadIdx.x;
    if (i < DIM * BATCH) {
        int k = i >> 5, b = i & 31;
        float v = L[k] * style[b * DIM + k];
        uint32_t bits;
        asm("cvt.rna.tf32.f32 %0, %1;" : "=r"(bits) : "f"(v));
        g_scaled[i] = bits;
    }
}

__device__ __forceinline__ uint32_t smem_u32(const void* p) {
    return (uint32_t)__cvta_generic_to_shared(p);
}
/* A loads: prefetch the full 256B-aligned block -> chunk c pulls chunk c+1's
   row-segment into L2 (row base is 2KB-aligned, so chunks pair within 256B). */
__device__ __forceinline__ void cp16_pf(uint32_t dst, const void* src) {
    asm volatile("cp.async.cg.shared.global.L2::256B [%0], [%1], 16;" :: "r"(dst), "l"(src));
}
__device__ __forceinline__ void cp16(uint32_t dst, const void* src) {
    asm volatile("cp.async.cg.shared.global [%0], [%1], 16;" :: "r"(dst), "l"(src));
}
__device__ __forceinline__ void cp_commit() {
    asm volatile("cp.async.commit_group;" ::: "memory");
}
__device__ __forceinline__ void cp_wait1() {
    asm volatile("cp.async.wait_group 1;" ::: "memory");
}
__device__ __forceinline__ void st_cs(float* p, float v) {
    asm volatile("st.global.cs.f32 [%0], %1;" :: "l"(p), "f"(v) : "memory");
}
__device__ __forceinline__ void mma_tf32(float* d, const uint32_t* a, uint32_t b0, uint32_t b1) {
    asm volatile(
        "mma.sync.aligned.m16n8k8.row.col.f32.tf32.tf32.f32 "
        "{%0,%1,%2,%3}, {%4,%5,%6,%7}, {%8,%9}, {%0,%1,%2,%3};"
        : "+f"(d[0]), "+f"(d[1]), "+f"(d[2]), "+f"(d[3])
        : "r"(a[0]), "r"(a[1]), "r"(a[2]), "r"(a[3]), "r"(b0), "r"(b1));
}

__global__ void __launch_bounds__(NTHREADS, 4)
gemm_kernel(const float* __restrict__ U, const float* __restrict__ mu, float* __restrict__ out)
{
    __shared__ uint32_t sA[2][MTILE * A_STRIDE];   /* 2 x 18 KB, padded rows */
    __shared__ uint32_t sB[2][KC * B_STRIDE];      /* 2 x  5 KB, padded rows */

    const int tid = threadIdx.x;
    const int wid = tid >> 5;
    const int lid = tid & 31;
    const int g   = lid >> 2;      /* groupID 0..7 */
    const int tg  = lid & 3;       /* thread-in-group 0..3 */
    const int mbase = blockIdx.x * MTILE;

    auto prefetch = [&](int c, int buf) {
        /* A: 128 rows x 128B, coalesced 16B lanes, L2::256B prefetch */
        const float* ubase = U + (size_t)mbase * DIM + c * KC;
        uint32_t adst = smem_u32(&sA[buf][0]);
        #pragma unroll
        for (int j = 0; j < 8; ++j) {
            int id  = j * NTHREADS + tid;
            int row = id >> 3, seg = id & 7;
            cp16_pf(adst + (uint32_t)(row * (A_STRIDE * 4) + seg * 16),
                    ubase + (size_t)row * DIM + seg * 4);
        }
        /* B: 32 k-rows x 128B, padded rows */
        const uint32_t* bsrc = g_scaled + c * KC * BATCH;
        uint32_t bdst = smem_u32(&sB[buf][0]);
        #pragma unroll
        for (int j = 0; j < 2; ++j) {
            int id  = j * NTHREADS + tid;
            int row = id >> 3, seg = id & 7;
            cp16(bdst + (uint32_t)(row * (B_STRIDE * 4) + seg * 16),
                 bsrc + (size_t)row * BATCH + seg * 4);
        }
    };

    float acc[2][4][4];
    #pragma unroll
    for (int mt = 0; mt < 2; ++mt)
        #pragma unroll
        for (int nt = 0; nt < 4; ++nt)
            #pragma unroll
            for (int r = 0; r < 4; ++r) acc[mt][nt][r] = 0.0f;

    prefetch(0, 0); cp_commit();
    prefetch(1, 1); cp_commit();

    for (int c = 0; c < NCHUNK; ++c) {
        cp_wait1();
        __syncthreads();
        const uint32_t* A = sA[c & 1];
        const uint32_t* B = sB[c & 1];

        #pragma unroll
        for (int ks = 0; ks < 4; ++ks) {
            uint32_t a[2][4], b[4][2];
            #pragma unroll
            for (int mt = 0; mt < 2; ++mt) {
                int rb = wid * 32 + mt * 16;
                /* +0x1000: RNE into tf32 (HW truncates low 13 bits) */
                a[mt][0] = A[(rb + g)     * A_STRIDE + ks * 8 + tg]     + 0x1000u;
                a[mt][1] = A[(rb + g + 8) * A_STRIDE + ks * 8 + tg]     + 0x1000u;
                a[mt][2] = A[(rb + g)     * A_STRIDE + ks * 8 + tg + 4] + 0x1000u;
                a[mt][3] = A[(rb + g + 8) * A_STRIDE + ks * 8 + tg + 4] + 0x1000u;
            }
            #pragma unroll
            for (int nt = 0; nt < 4; ++nt) {
                b[nt][0] = B[(ks * 8 + tg)     * B_STRIDE + nt * 8 + g];
                b[nt][1] = B[(ks * 8 + tg + 4) * B_STRIDE + nt * 8 + g];
            }
            #pragma unroll
            for (int mt = 0; mt < 2; ++mt)
                #pragma unroll
                for (int nt = 0; nt < 4; ++nt)
                    mma_tf32(acc[mt][nt], a[mt], b[nt][0], b[nt][1]);
        }

        __syncthreads();
        if (c + 2 < NCHUNK) prefetch(c + 2, c & 1);
        cp_commit();   /* possibly-empty group keeps wait_group accounting simple */
    }

    /* epilogue: add mu, store out[b][m] with evict-first (write-once data) */
    #pragma unroll
    for (int mt = 0; mt < 2; ++mt) {
        int m0 = mbase + wid * 32 + mt * 16 + g;
        float mu0 = __ldg(&mu[m0]);
        float mu1 = __ldg(&mu[m0 + 8]);
        #pragma unroll
        for (int nt = 0; nt < 4; ++nt) {
            int b0 = nt * 8 + 2 * tg;
            st_cs(&out[(size_t)b0       * M_TOTAL + m0],     acc[mt][nt][0] + mu0);
            st_cs(&out[(size_t)(b0 + 1) * M_TOTAL + m0],     acc[mt][nt][1] + mu0);
            st_cs(&out[(size_t)b0       * M_TOTAL + m0 + 8], acc[mt][nt][2] + mu1);
            st_cs(&out[(size_t)(b0 + 1) * M_TOTAL + m0 + 8], acc[mt][nt][3] + mu1);
        }
    }
}

extern "C" void kernel_launch(void* const* d_in, const int* in_sizes, int n_in,
                              void* d_out, int out_size) {
    const float *style = nullptr, *U = nullptr, *L = nullptr, *mu = nullptr;
    for (int i = 0; i < n_in; ++i) {
        switch (in_sizes[i]) {
            case BATCH * DIM:   style = (const float*)d_in[i]; break;
            case M_TOTAL * DIM: U     = (const float*)d_in[i]; break;
            case DIM:           L     = (const float*)d_in[i]; break;
            case M_TOTAL:       mu    = (const float*)d_in[i]; break;
            default: break;
        }
    }
    float* out = (float*)d_out;

    prep_kernel<<<(DIM * BATCH + 255) / 256, 256>>>(style, L);
    gemm_kernel<<<M_TOTAL / MTILE, NTHREADS>>>(U, mu, out);
}